// round 1
// baseline (speedup 1.0000x reference)
#include <cuda_runtime.h>
#include <cuda_bf16.h>
#include <math.h>

// Problem constants
#define MEM    1024
#define LSEQ   512
#define BATCH  128
#define KIN    512
#define MROWS  (BATCH * LSEQ)   // 65536
#define NCOLS  (2 * MEM)        // 2048

// GEMM tiling
#define BM 128
#define BN 128
#define BK 32
#define SDIM (BK + 8)                               // padded k-stride (bf16 elems)
#define STAGE_ELEMS (2 * BM * SDIM + 2 * BN * SDIM) // hi+lo for A and B
#define SMEM_BYTES  (2 * STAGE_ELEMS * 2)           // 2 stages * elems * 2B = 81920

// Scratch: in_emb post-epilogue. cols [0,1024) = soma_bias, [1024,2048) = i_o.
__device__ float g_emb[(size_t)MROWS * NCOLS];

__device__ __forceinline__ void mma_bf16(float c[4], const unsigned a[4], const unsigned b[2]) {
    asm volatile(
        "mma.sync.aligned.m16n8k16.row.col.f32.bf16.bf16.f32 "
        "{%0,%1,%2,%3}, {%4,%5,%6,%7}, {%8,%9}, {%0,%1,%2,%3};\n"
        : "+f"(c[0]), "+f"(c[1]), "+f"(c[2]), "+f"(c[3])
        : "r"(a[0]), "r"(a[1]), "r"(a[2]), "r"(a[3]), "r"(b[0]), "r"(b[1]));
}

// C[m,n] = sum_k U[m,k]*W[n,k] + bias[n]; fp32 accuracy via bf16 hi/lo split (3 MMAs).
// Epilogue: n <  MEM : g_emb = 5*tanh(c/5)   (soma_bias)
//           n >= MEM : g_emb = c             (i_o)
__global__ void __launch_bounds__(256, 1) gemm_split_kernel(
    const float* __restrict__ U,
    const float* __restrict__ W,
    const float* __restrict__ bias)
{
    extern __shared__ __nv_bfloat16 sm[];
    const int tid  = threadIdx.x;
    const int warp = tid >> 5;
    const int lane = tid & 31;
    const int q    = lane >> 2;  // 0..7
    const int c4   = lane & 3;   // 0..3
    const int m0 = blockIdx.y * BM;
    const int n0 = blockIdx.x * BN;
    const int wm = (warp >> 2) * 64;  // warp m-offset (2 warp-rows)
    const int wn = (warp & 3) * 32;   // warp n-offset (4 warp-cols)

    // SMEM stage pointers: [stage][hi/lo]
    __nv_bfloat16* As0h = sm;
    auto As = [&](int st, int hl) { return sm + (size_t)st * STAGE_ELEMS + (size_t)hl * (BM * SDIM); };
    auto Bs = [&](int st, int hl) { return sm + (size_t)st * STAGE_ELEMS + 2 * BM * SDIM + (size_t)hl * (BN * SDIM); };
    (void)As0h;

    // Global-load assignment: 1024 float4 per tile, 4 per thread.
    int lrow[4], lcw[4];
    #pragma unroll
    for (int i = 0; i < 4; i++) {
        int idx = tid + i * 256;
        lrow[i] = idx >> 3;         // row within tile (0..127)
        lcw[i]  = (idx & 7) * 4;    // k-offset within chunk (0..28, step 4)
    }

    float4 ra[4], rb[4];
    auto loadg = [&](int k0) {
        #pragma unroll
        for (int i = 0; i < 4; i++) {
            ra[i] = *reinterpret_cast<const float4*>(U + (size_t)(m0 + lrow[i]) * KIN + k0 + lcw[i]);
            rb[i] = *reinterpret_cast<const float4*>(W + (size_t)(n0 + lrow[i]) * KIN + k0 + lcw[i]);
        }
    };

    auto split_sts = [&](int st) {
        __nv_bfloat16* ah = As(st, 0); __nv_bfloat16* al = As(st, 1);
        __nv_bfloat16* bh = Bs(st, 0); __nv_bfloat16* bl = Bs(st, 1);
        #pragma unroll
        for (int i = 0; i < 4; i++) {
            const float* va = reinterpret_cast<const float*>(&ra[i]);
            const float* vb = reinterpret_cast<const float*>(&rb[i]);
            int off = lrow[i] * SDIM + lcw[i];
            #pragma unroll
            for (int j = 0; j < 4; j += 2) {
                float x0 = va[j], x1 = va[j + 1];
                __nv_bfloat16 h0 = __float2bfloat16(x0);
                __nv_bfloat16 h1 = __float2bfloat16(x1);
                __nv_bfloat16 l0 = __float2bfloat16(x0 - __bfloat162float(h0));
                __nv_bfloat16 l1 = __float2bfloat16(x1 - __bfloat162float(h1));
                *reinterpret_cast<__nv_bfloat162*>(&ah[off + j]) = __nv_bfloat162(h0, h1);
                *reinterpret_cast<__nv_bfloat162*>(&al[off + j]) = __nv_bfloat162(l0, l1);
                x0 = vb[j]; x1 = vb[j + 1];
                h0 = __float2bfloat16(x0);
                h1 = __float2bfloat16(x1);
                l0 = __float2bfloat16(x0 - __bfloat162float(h0));
                l1 = __float2bfloat16(x1 - __bfloat162float(h1));
                *reinterpret_cast<__nv_bfloat162*>(&bh[off + j]) = __nv_bfloat162(h0, h1);
                *reinterpret_cast<__nv_bfloat162*>(&bl[off + j]) = __nv_bfloat162(l0, l1);
            }
        }
    };

    float acc[4][4][4];
    #pragma unroll
    for (int mi = 0; mi < 4; mi++)
        #pragma unroll
        for (int ni = 0; ni < 4; ni++)
            #pragma unroll
            for (int r = 0; r < 4; r++) acc[mi][ni][r] = 0.0f;

    auto compute = [&](int st) {
        const __nv_bfloat16* Ah = As(st, 0); const __nv_bfloat16* Al = As(st, 1);
        const __nv_bfloat16* Bh = Bs(st, 0); const __nv_bfloat16* Bl = Bs(st, 1);
        #pragma unroll
        for (int kk = 0; kk < BK; kk += 16) {
            unsigned ah[4][4], al[4][4], bh[4][2], bl[4][2];
            #pragma unroll
            for (int mi = 0; mi < 4; mi++) {
                int base = (wm + mi * 16 + q) * SDIM + kk + 2 * c4;
                ah[mi][0] = *reinterpret_cast<const unsigned*>(&Ah[base]);
                ah[mi][1] = *reinterpret_cast<const unsigned*>(&Ah[base + 8 * SDIM]);
                ah[mi][2] = *reinterpret_cast<const unsigned*>(&Ah[base + 8]);
                ah[mi][3] = *reinterpret_cast<const unsigned*>(&Ah[base + 8 * SDIM + 8]);
                al[mi][0] = *reinterpret_cast<const unsigned*>(&Al[base]);
                al[mi][1] = *reinterpret_cast<const unsigned*>(&Al[base + 8 * SDIM]);
                al[mi][2] = *reinterpret_cast<const unsigned*>(&Al[base + 8]);
                al[mi][3] = *reinterpret_cast<const unsigned*>(&Al[base + 8 * SDIM + 8]);
            }
            #pragma unroll
            for (int ni = 0; ni < 4; ni++) {
                int base = (wn + ni * 8 + q) * SDIM + kk + 2 * c4;
                bh[ni][0] = *reinterpret_cast<const unsigned*>(&Bh[base]);
                bh[ni][1] = *reinterpret_cast<const unsigned*>(&Bh[base + 8]);
                bl[ni][0] = *reinterpret_cast<const unsigned*>(&Bl[base]);
                bl[ni][1] = *reinterpret_cast<const unsigned*>(&Bl[base + 8]);
            }
            #pragma unroll
            for (int mi = 0; mi < 4; mi++)
                #pragma unroll
                for (int ni = 0; ni < 4; ni++) {
                    mma_bf16(acc[mi][ni], ah[mi], bh[ni]);  // hi*hi
                    mma_bf16(acc[mi][ni], al[mi], bh[ni]);  // lo*hi
                    mma_bf16(acc[mi][ni], ah[mi], bl[ni]);  // hi*lo
                }
        }
    };

    loadg(0);
    split_sts(0);
    __syncthreads();

    for (int c = 0; c < KIN / BK; c++) {
        int st = c & 1;
        if (c < KIN / BK - 1) loadg((c + 1) * BK);
        compute(st);
        if (c < KIN / BK - 1) split_sts(st ^ 1);
        __syncthreads();
    }

    // Epilogue: bias + soma_bias transform for first half, store fp32 scratch
    #pragma unroll
    for (int mi = 0; mi < 4; mi++) {
        int gm = m0 + wm + mi * 16 + q;
        #pragma unroll
        for (int ni = 0; ni < 4; ni++) {
            int gn = n0 + wn + ni * 8 + c4 * 2;
            float b0 = bias[gn], b1 = bias[gn + 1];
            #pragma unroll
            for (int rr = 0; rr < 2; rr++) {
                int row = gm + rr * 8;
                float v0 = acc[mi][ni][rr * 2 + 0] + b0;
                float v1 = acc[mi][ni][rr * 2 + 1] + b1;
                if (gn < MEM) {  // soma_bias = 5*tanh(c/5)
                    v0 = 5.0f * tanhf(v0 * 0.2f);
                    v1 = 5.0f * tanhf(v1 * 0.2f);
                }
                *reinterpret_cast<float2*>(&g_emb[(size_t)row * NCOLS + gn]) = make_float2(v0, v1);
            }
        }
    }
}

// One thread per (b, mem). Sequential over t; coalesced across mem.
__global__ void __launch_bounds__(256) scan_kernel(
    const float* __restrict__ h0, float* __restrict__ out)
{
    int idx = blockIdx.x * blockDim.x + threadIdx.x;  // 0 .. 131071
    int b = idx >> 10;
    int m = idx & (MEM - 1);
    const float* ebase = g_emb + (size_t)b * LSEQ * NCOLS + m;
    float* ho = out + (size_t)b * LSEQ * MEM + m;

    float hf = h0[idx];               // h0[0][b][m]
    float hs = h0[BATCH * MEM + idx]; // h0[1][b][m]

    #pragma unroll 4
    for (int t = 0; t < LSEQ; t++) {
        float sb = ebase[(size_t)t * NCOLS];
        float io = ebase[(size_t)t * NCOLS + MEM];
        float d = hs + 0.4f;
        float arg = io + 4.0f * hf - 7.0f * (d * d) + sb;
        float hfn = tanhf(arg);
        // eps uses OLD hf; hs update uses OLD hf, then hf <- hfn
        float eps = 0.9f + 0.9f * (1.0f / (1.0f + expf((0.5f - hf) * 10.0f)));
        hs = (1.0f - eps) * hs + eps * hf;
        hf = hfn;
        ho[(size_t)t * MEM] = hfn;
    }
    out[(size_t)BATCH * LSEQ * MEM + idx] = hf;  // hf_last
}

extern "C" void kernel_launch(void* const* d_in, const int* in_sizes, int n_in,
                              void* d_out, int out_size) {
    const float* u    = (const float*)d_in[0];  // [128, 512, 512]
    const float* h0   = (const float*)d_in[1];  // [2, 128, 1024]
    const float* W    = (const float*)d_in[2];  // [2048, 512]
    const float* bias = (const float*)d_in[3];  // [2048]
    float* out = (float*)d_out;                 // h_t [128,512,1024] ++ hf_last [128,1024]

    cudaFuncSetAttribute(gemm_split_kernel,
                         cudaFuncAttributeMaxDynamicSharedMemorySize, SMEM_BYTES);

    dim3 grid(NCOLS / BN, MROWS / BM);  // (16, 512): n-inner raster -> u-tile L2 reuse
    gemm_split_kernel<<<grid, 256, SMEM_BYTES>>>(u, W, bias);
    scan_kernel<<<(BATCH * MEM) / 256, 256>>>(h0, out);
}

// round 3
// speedup vs baseline: 1.1874x; 1.1874x over previous
#include <cuda_runtime.h>
#include <cuda_bf16.h>
#include <math.h>
#include <stdint.h>

// Problem constants
#define MEM    1024
#define LSEQ   512
#define BATCH  128
#define KIN    512
#define MROWS  (BATCH * LSEQ)   // 65536
#define NCOLS  (2 * MEM)        // 2048

// GEMM tiling (mma.sync HMMA path; tcgen05 PTX rejected by this toolchain target)
#define BM 128
#define BN 128
#define BK 64
#define NCHUNK (KIN / BK)       // 8
#define STAGES 3
#define SUB_BYTES 16384                      // one 128x64 bf16 sub-tile (128B rows)
#define STAGE_BYTES (4 * SUB_BYTES)          // Ah | Al | Bh | Bl = 64KB
#define SMEM_TOTAL (STAGES * STAGE_BYTES)    // 192KB

// Scratch
__device__ float g_emb[(size_t)MROWS * NCOLS];                 // 512MB
__device__ __nv_bfloat16 g_uh[(size_t)MROWS * KIN];            // 64MB
__device__ __nv_bfloat16 g_ul[(size_t)MROWS * KIN];            // 64MB
__device__ __nv_bfloat16 g_wh[(size_t)NCOLS * KIN];            // 2MB
__device__ __nv_bfloat16 g_wl[(size_t)NCOLS * KIN];            // 2MB

// ---------------------------------------------------------------- helpers
__device__ __forceinline__ uint32_t smem_u32(const void* p) {
    uint32_t a;
    asm("{ .reg .u64 t; cvta.to.shared.u64 t, %1; cvt.u32.u64 %0, t; }" : "=r"(a) : "l"(p));
    return a;
}

__device__ __forceinline__ void mma_bf16(float c[4], const unsigned a[4], const unsigned b[2]) {
    asm volatile(
        "mma.sync.aligned.m16n8k16.row.col.f32.bf16.bf16.f32 "
        "{%0,%1,%2,%3}, {%4,%5,%6,%7}, {%8,%9}, {%0,%1,%2,%3};\n"
        : "+f"(c[0]), "+f"(c[1]), "+f"(c[2]), "+f"(c[3])
        : "r"(a[0]), "r"(a[1]), "r"(a[2]), "r"(a[3]), "r"(b[0]), "r"(b[1]));
}

__device__ __forceinline__ void ldm4(unsigned r[4], uint32_t addr) {
    asm volatile("ldmatrix.sync.aligned.m8n8.x4.shared.b16 {%0,%1,%2,%3}, [%4];"
                 : "=r"(r[0]), "=r"(r[1]), "=r"(r[2]), "=r"(r[3]) : "r"(addr));
}

__device__ __forceinline__ void cp16(uint32_t s, const void* g) {
    asm volatile("cp.async.cg.shared.global [%0], [%1], 16;" :: "r"(s), "l"(g));
}
#define CP_COMMIT() asm volatile("cp.async.commit_group;" ::: "memory")
#define CP_WAIT1()  asm volatile("cp.async.wait_group 1;" ::: "memory")
#define CP_WAIT0()  asm volatile("cp.async.wait_group 0;" ::: "memory")

// ---------------------------------------------------------------- split kernel
// fp32 -> (bf16 hi, bf16 lo) with lo = rn(x - float(hi)).
__device__ __forceinline__ void split4(float4 v, uint2& ho, uint2& lo) {
    __nv_bfloat162 h0 = __floats2bfloat162_rn(v.x, v.y);
    __nv_bfloat162 h1 = __floats2bfloat162_rn(v.z, v.w);
    float2 f0 = __bfloat1622float2(h0), f1 = __bfloat1622float2(h1);
    __nv_bfloat162 l0 = __floats2bfloat162_rn(v.x - f0.x, v.y - f0.y);
    __nv_bfloat162 l1 = __floats2bfloat162_rn(v.z - f1.x, v.w - f1.y);
    ho = make_uint2(*reinterpret_cast<uint32_t*>(&h0), *reinterpret_cast<uint32_t*>(&h1));
    lo = make_uint2(*reinterpret_cast<uint32_t*>(&l0), *reinterpret_cast<uint32_t*>(&l1));
}

__global__ void __launch_bounds__(256) split_u_kernel(const float4* __restrict__ src) {
    size_t i = (size_t)blockIdx.x * 256 + threadIdx.x;   // over MROWS*KIN/4
    uint2 h, l;
    split4(src[i], h, l);
    reinterpret_cast<uint2*>(g_uh)[i] = h;
    reinterpret_cast<uint2*>(g_ul)[i] = l;
}

__global__ void __launch_bounds__(256) split_w_kernel(const float4* __restrict__ src) {
    size_t i = (size_t)blockIdx.x * 256 + threadIdx.x;   // over NCOLS*KIN/4
    uint2 h, l;
    split4(src[i], h, l);
    reinterpret_cast<uint2*>(g_wh)[i] = h;
    reinterpret_cast<uint2*>(g_wl)[i] = l;
}

// ---------------------------------------------------------------- GEMM kernel
// C[m,n] = sum_k U[m,k]*W[n,k] + bias[n]; 3-pass bf16 hi/lo for fp32 accuracy.
// n-tile < MEM : g_emb = 5*tanh(c/5) (soma_bias);  else : g_emb = c (i_o)
__global__ void __launch_bounds__(256, 1) gemm_kernel(const float* __restrict__ bias)
{
    extern __shared__ char dsm[];
    const uint32_t smb = smem_u32(dsm);
    const int tid  = threadIdx.x;
    const int warp = tid >> 5;
    const int lane = tid & 31;
    const int m0 = blockIdx.y * BM;
    const int n0 = blockIdx.x * BN;
    const int wm = (warp >> 2) * 64;  // warp m-offset
    const int wn = (warp & 3) * 32;   // warp n-offset

    // cp.async per-thread assignment: 4 rows' chunks per sub-tile
    int prow[4], pch[4];
    uint32_t psoff[4];
    #pragma unroll
    for (int i = 0; i < 4; i++) {
        int idx = tid + i * 256;          // 0..1023
        prow[i] = idx >> 3;               // 0..127
        pch[i]  = idx & 7;                // chunk 0..7 (16B each)
        psoff[i] = (uint32_t)(prow[i] * 128 + ((pch[i] ^ (prow[i] & 7)) << 4));
    }

    auto issue = [&](int c) {
        int st = c % STAGES;
        int k0 = c * BK;
        uint32_t base = smb + (uint32_t)st * STAGE_BYTES;
        #pragma unroll
        for (int i = 0; i < 4; i++) {
            size_t goffA = (size_t)(m0 + prow[i]) * KIN + k0 + pch[i] * 8;
            size_t goffB = (size_t)(n0 + prow[i]) * KIN + k0 + pch[i] * 8;
            cp16(base                 + psoff[i], g_uh + goffA);
            cp16(base + 1 * SUB_BYTES + psoff[i], g_ul + goffA);
            cp16(base + 2 * SUB_BYTES + psoff[i], g_wh + goffB);
            cp16(base + 3 * SUB_BYTES + psoff[i], g_wl + goffB);
        }
        CP_COMMIT();
    };

    float acc[4][4][4];
    #pragma unroll
    for (int mi = 0; mi < 4; mi++)
        #pragma unroll
        for (int ni = 0; ni < 4; ni++)
            #pragma unroll
            for (int r = 0; r < 4; r++) acc[mi][ni][r] = 0.0f;

    // ldmatrix address components (lane-invariant parts precomputed)
    int arow[4], brow[2];
    #pragma unroll
    for (int mi = 0; mi < 4; mi++) arow[mi] = wm + mi * 16 + (lane & 15);
    #pragma unroll
    for (int nj = 0; nj < 2; nj++)
        brow[nj] = wn + nj * 16 + (lane & 7) + ((lane >> 4) << 3);
    const int acsub = lane >> 4;          // A chunk sub-index
    const int bcsub = (lane >> 3) & 1;    // B chunk sub-index

    auto compute = [&](int st) {
        uint32_t base = smb + (uint32_t)st * STAGE_BYTES;
        #pragma unroll
        for (int kk = 0; kk < 4; kk++) {  // four k16 steps in BK=64
            unsigned ah[4][4], al[4][4], bh[2][4], bl[2][4];
            #pragma unroll
            for (int mi = 0; mi < 4; mi++) {
                uint32_t off = (uint32_t)(arow[mi] * 128 +
                               ((((kk << 1) + acsub) ^ (arow[mi] & 7)) << 4));
                ldm4(ah[mi], base + off);
                ldm4(al[mi], base + SUB_BYTES + off);
            }
            #pragma unroll
            for (int nj = 0; nj < 2; nj++) {
                uint32_t off = (uint32_t)(brow[nj] * 128 +
                               ((((kk << 1) + bcsub) ^ (brow[nj] & 7)) << 4));
                ldm4(bh[nj], base + 2 * SUB_BYTES + off);
                ldm4(bl[nj], base + 3 * SUB_BYTES + off);
            }
            #pragma unroll
            for (int mi = 0; mi < 4; mi++)
                #pragma unroll
                for (int ni = 0; ni < 4; ni++) {
                    const unsigned* bhp = &bh[ni >> 1][(ni & 1) * 2];
                    const unsigned* blp = &bl[ni >> 1][(ni & 1) * 2];
                    mma_bf16(acc[mi][ni], ah[mi], bhp);  // hi*hi
                    mma_bf16(acc[mi][ni], al[mi], bhp);  // lo*hi
                    mma_bf16(acc[mi][ni], ah[mi], blp);  // hi*lo
                }
        }
    };

    issue(0);
    issue(1);

    for (int c = 0; c < NCHUNK; c++) {
        if (c == NCHUNK - 1) { CP_WAIT0(); } else { CP_WAIT1(); }
        __syncthreads();
        if (c + 2 < NCHUNK) issue(c + 2);
        compute(c % STAGES);
    }

    // Epilogue: lane l of warp -> rows wm+mi*16+{q, q+8}, cols wn+ni*8+2*c4
    const int q  = lane >> 2;
    const int c4 = lane & 3;
    const bool soma = (n0 < MEM);
    #pragma unroll
    for (int mi = 0; mi < 4; mi++) {
        int gm = m0 + wm + mi * 16 + q;
        #pragma unroll
        for (int ni = 0; ni < 4; ni++) {
            int gn = n0 + wn + ni * 8 + c4 * 2;
            float b0 = __ldg(bias + gn), b1 = __ldg(bias + gn + 1);
            #pragma unroll
            for (int rr = 0; rr < 2; rr++) {
                int row = gm + rr * 8;
                float v0 = acc[mi][ni][rr * 2 + 0] + b0;
                float v1 = acc[mi][ni][rr * 2 + 1] + b1;
                if (soma) {
                    v0 = 5.0f * tanhf(v0 * 0.2f);
                    v1 = 5.0f * tanhf(v1 * 0.2f);
                }
                *reinterpret_cast<float2*>(&g_emb[(size_t)row * NCOLS + gn]) =
                    make_float2(v0, v1);
            }
        }
    }
}

// ---------------------------------------------------------------- scan kernel
// 4 (b,mem) lanes per thread (float4), explicit depth-2 prefetch for MLP.
__device__ __forceinline__ void scan_step(float& hf, float& hs, float sb, float io,
                                          float& outv) {
    float d = hs + 0.4f;
    float arg = io + 4.0f * hf - 7.0f * (d * d) + sb;
    float hfn = tanhf(arg);
    float eps = 0.9f + 0.9f * (1.0f / (1.0f + __expf((0.5f - hf) * 10.0f)));
    hs = (1.0f - eps) * hs + eps * hf;
    hf = hfn;
    outv = hfn;
}

__global__ void __launch_bounds__(256) scan_kernel(
    const float* __restrict__ h0, float* __restrict__ out)
{
    int idx = blockIdx.x * 256 + threadIdx.x;  // 0 .. 32767
    int b = idx >> 8;
    int m4 = (idx & 255) << 2;

    const char* eb = (const char*)(g_emb + (size_t)b * LSEQ * NCOLS + m4);
    float* ho = out + (size_t)b * LSEQ * MEM + m4;

    float4 hf = *reinterpret_cast<const float4*>(h0 + (size_t)b * MEM + m4);
    float4 hs = *reinterpret_cast<const float4*>(h0 + (size_t)BATCH * MEM + (size_t)b * MEM + m4);

    float4 sb0 = *reinterpret_cast<const float4*>(eb);
    float4 io0 = *reinterpret_cast<const float4*>(eb + MEM * 4);
    float4 sb1 = *reinterpret_cast<const float4*>(eb + (size_t)NCOLS * 4);
    float4 io1 = *reinterpret_cast<const float4*>(eb + (size_t)NCOLS * 4 + MEM * 4);

    #pragma unroll 2
    for (int t = 0; t < LSEQ; t++) {
        float4 sb2 = sb1, io2 = io1;
        if (t + 2 < LSEQ) {
            const char* p = eb + (size_t)(t + 2) * NCOLS * 4;
            sb2 = *reinterpret_cast<const float4*>(p);
            io2 = *reinterpret_cast<const float4*>(p + MEM * 4);
        }
        float4 o;
        scan_step(hf.x, hs.x, sb0.x, io0.x, o.x);
        scan_step(hf.y, hs.y, sb0.y, io0.y, o.y);
        scan_step(hf.z, hs.z, sb0.z, io0.z, o.z);
        scan_step(hf.w, hs.w, sb0.w, io0.w, o.w);
        *reinterpret_cast<float4*>(ho + (size_t)t * MEM) = o;
        sb0 = sb1; io0 = io1;
        sb1 = sb2; io1 = io2;
    }
    *reinterpret_cast<float4*>(out + (size_t)BATCH * LSEQ * MEM + (size_t)b * MEM + m4) = hf;
}

// ---------------------------------------------------------------- launch
extern "C" void kernel_launch(void* const* d_in, const int* in_sizes, int n_in,
                              void* d_out, int out_size) {
    const float* u    = (const float*)d_in[0];  // [128, 512, 512]
    const float* h0   = (const float*)d_in[1];  // [2, 128, 1024]
    const float* W    = (const float*)d_in[2];  // [2048, 512]
    const float* bias = (const float*)d_in[3];  // [2048]
    float* out = (float*)d_out;                 // h_t [128,512,1024] ++ hf_last [128,1024]

    cudaFuncSetAttribute(gemm_kernel,
                         cudaFuncAttributeMaxDynamicSharedMemorySize, SMEM_TOTAL);

    split_u_kernel<<<(MROWS * KIN / 4) / 256, 256>>>((const float4*)u);
    split_w_kernel<<<(NCOLS * KIN / 4) / 256, 256>>>((const float4*)W);

    dim3 grid(NCOLS / BN, MROWS / BM);  // (16, 512): x-fastest -> A-tile L2 reuse
    gemm_kernel<<<grid, 256, SMEM_TOTAL>>>(bias);

    scan_kernel<<<(BATCH * MEM / 4) / 256, 256>>>(h0, out);
}

// round 5
// speedup vs baseline: 1.3390x; 1.1277x over previous
#include <cuda_runtime.h>
#include <cuda_bf16.h>
#include <math.h>
#include <stdint.h>

// Problem constants
#define MEM    1024
#define LSEQ   512
#define BATCH  128
#define KIN    512
#define MROWS  (BATCH * LSEQ)   // 65536
#define NCOLS  (2 * MEM)        // 2048

// GEMM tiling (mma.sync HMMA path; tcgen05 unavailable on this toolchain target)
#define BM 128
#define BN 256
#define BK 32
#define NCHUNK (KIN / BK)       // 16
#define STAGES 4
// per-stage SMEM layout (bf16, 64B rows of 32 elems):
#define AH_OFF 0
#define AL_OFF 8192
#define BH_OFF 16384
#define BL_OFF 32768
#define STAGE_BYTES 49152
#define SMEM_TOTAL (STAGES * STAGE_BYTES)   // 192KB

// Scratch
__device__ float g_emb[(size_t)MROWS * NCOLS];                 // 512MB
__device__ __nv_bfloat16 g_uh[(size_t)MROWS * KIN];            // 64MB
__device__ __nv_bfloat16 g_ul[(size_t)MROWS * KIN];            // 64MB
__device__ __nv_bfloat16 g_wh[(size_t)NCOLS * KIN];            // 2MB
__device__ __nv_bfloat16 g_wl[(size_t)NCOLS * KIN];            // 2MB

// ---------------------------------------------------------------- helpers
__device__ __forceinline__ uint32_t smem_u32(const void* p) {
    uint32_t a;
    asm("{ .reg .u64 t; cvta.to.shared.u64 t, %1; cvt.u32.u64 %0, t; }" : "=r"(a) : "l"(p));
    return a;
}

__device__ __forceinline__ void mma_bf16(float c[4], const unsigned a[4], const unsigned b[2]) {
    asm volatile(
        "mma.sync.aligned.m16n8k16.row.col.f32.bf16.bf16.f32 "
        "{%0,%1,%2,%3}, {%4,%5,%6,%7}, {%8,%9}, {%0,%1,%2,%3};\n"
        : "+f"(c[0]), "+f"(c[1]), "+f"(c[2]), "+f"(c[3])
        : "r"(a[0]), "r"(a[1]), "r"(a[2]), "r"(a[3]), "r"(b[0]), "r"(b[1]));
}

__device__ __forceinline__ void ldm4(unsigned r[4], uint32_t addr) {
    asm volatile("ldmatrix.sync.aligned.m8n8.x4.shared.b16 {%0,%1,%2,%3}, [%4];"
                 : "=r"(r[0]), "=r"(r[1]), "=r"(r[2]), "=r"(r[3]) : "r"(addr));
}

__device__ __forceinline__ void cp16(uint32_t s, const void* g) {
    asm volatile("cp.async.cg.shared.global [%0], [%1], 16;" :: "r"(s), "l"(g));
}
#define CP_COMMIT() asm volatile("cp.async.commit_group;" ::: "memory")
#define CP_WAIT2()  asm volatile("cp.async.wait_group 2;" ::: "memory")
#define CP_WAIT1()  asm volatile("cp.async.wait_group 1;" ::: "memory")
#define CP_WAIT0()  asm volatile("cp.async.wait_group 0;" ::: "memory")

// Fast accurate tanh: 1 - 2/(exp(2x)+1). NaN-free at +/-inf of exp; abs err ~6e-8.
__device__ __forceinline__ float ftanh(float x) {
    float e = __expf(x + x);
    return 1.0f - __fdividef(2.0f, e + 1.0f);
}

// swizzled SMEM byte offset for (row, 16B-chunk) with 64B rows
__device__ __forceinline__ uint32_t soff(int row, int ch) {
    return (uint32_t)(row * 64 + ((ch ^ ((row >> 1) & 3)) << 4));
}

// ---------------------------------------------------------------- split kernels
__device__ __forceinline__ void split4(float4 v, uint2& ho, uint2& lo) {
    __nv_bfloat162 h0 = __floats2bfloat162_rn(v.x, v.y);
    __nv_bfloat162 h1 = __floats2bfloat162_rn(v.z, v.w);
    float2 f0 = __bfloat1622float2(h0), f1 = __bfloat1622float2(h1);
    __nv_bfloat162 l0 = __floats2bfloat162_rn(v.x - f0.x, v.y - f0.y);
    __nv_bfloat162 l1 = __floats2bfloat162_rn(v.z - f1.x, v.w - f1.y);
    ho = make_uint2(*reinterpret_cast<uint32_t*>(&h0), *reinterpret_cast<uint32_t*>(&h1));
    lo = make_uint2(*reinterpret_cast<uint32_t*>(&l0), *reinterpret_cast<uint32_t*>(&l1));
}

__global__ void __launch_bounds__(256) split_u_kernel(const float4* __restrict__ src) {
    size_t i = (size_t)blockIdx.x * 256 + threadIdx.x;
    uint2 h, l;
    split4(src[i], h, l);
    reinterpret_cast<uint2*>(g_uh)[i] = h;
    reinterpret_cast<uint2*>(g_ul)[i] = l;
}

__global__ void __launch_bounds__(256) split_w_kernel(const float4* __restrict__ src) {
    size_t i = (size_t)blockIdx.x * 256 + threadIdx.x;
    uint2 h, l;
    split4(src[i], h, l);
    reinterpret_cast<uint2*>(g_wh)[i] = h;
    reinterpret_cast<uint2*>(g_wl)[i] = l;
}

// ---------------------------------------------------------------- GEMM kernel
// C[m,n] = sum_k U[m,k]*W[n,k] + bias[n]; 3-pass bf16 hi/lo for fp32 accuracy.
// n < MEM : g_emb = 5*tanh(c/5) (soma_bias);  else : g_emb = c (i_o)
__global__ void __launch_bounds__(256, 1) gemm_kernel(const float* __restrict__ bias)
{
    extern __shared__ char dsm[];
    const uint32_t smb = smem_u32(dsm);
    const int tid  = threadIdx.x;
    const int warp = tid >> 5;
    const int lane = tid & 31;
    const int m0 = blockIdx.y * BM;
    const int n0 = blockIdx.x * BN;
    const int wm = (warp >> 2) * 64;  // warp m-offset (2 warp-rows of 64)
    const int wn = (warp & 3) * 64;   // warp n-offset (4 warp-cols of 64)

    auto issue = [&](int c) {
        uint32_t base = smb + (uint32_t)(c & 3) * STAGE_BYTES;
        int k0 = c * BK;
        #pragma unroll
        for (int i = 0; i < 2; i++) {            // A: 512 chunks hi + 512 lo
            int idx = tid + i * 256;
            int r = idx >> 2, ch = idx & 3;
            uint32_t so = soff(r, ch);
            size_t go = (size_t)(m0 + r) * KIN + k0 + ch * 8;
            cp16(base + AH_OFF + so, g_uh + go);
            cp16(base + AL_OFF + so, g_ul + go);
        }
        #pragma unroll
        for (int i = 0; i < 4; i++) {            // B: 1024 chunks hi + 1024 lo
            int idx = tid + i * 256;
            int r = idx >> 2, ch = idx & 3;
            uint32_t so = soff(r, ch);
            size_t go = (size_t)(n0 + r) * KIN + k0 + ch * 8;
            cp16(base + BH_OFF + so, g_wh + go);
            cp16(base + BL_OFF + so, g_wl + go);
        }
        CP_COMMIT();
    };

    float acc[4][8][4];
    #pragma unroll
    for (int mi = 0; mi < 4; mi++)
        #pragma unroll
        for (int ni = 0; ni < 8; ni++)
            #pragma unroll
            for (int r = 0; r < 4; r++) acc[mi][ni][r] = 0.0f;

    auto compute = [&](int st) {
        uint32_t base = smb + (uint32_t)st * STAGE_BYTES;
        #pragma unroll
        for (int kk = 0; kk < 2; kk++) {   // two k16 steps in BK=32
            unsigned ah[4][4], al[4][4];
            #pragma unroll
            for (int mi = 0; mi < 4; mi++) {
                int row = wm + mi * 16 + (lane & 15);
                int ch  = 2 * kk + (lane >> 4);
                uint32_t off = soff(row, ch);
                ldm4(ah[mi], base + AH_OFF + off);
                ldm4(al[mi], base + AL_OFF + off);
            }
            #pragma unroll
            for (int h = 0; h < 2; h++) {  // n in halves of 32 to cap registers
                unsigned bh[2][4], bl[2][4];
                #pragma unroll
                for (int nj = 0; nj < 2; nj++) {
                    int row = wn + h * 32 + nj * 16 + (lane & 7) + ((lane >> 4) << 3);
                    int ch  = 2 * kk + ((lane >> 3) & 1);
                    uint32_t off = soff(row, ch);
                    ldm4(bh[nj], base + BH_OFF + off);
                    ldm4(bl[nj], base + BL_OFF + off);
                }
                #pragma unroll
                for (int mi = 0; mi < 4; mi++)
                    #pragma unroll
                    for (int nq = 0; nq < 4; nq++) {
                        int ni = h * 4 + nq;
                        const unsigned* bhp = &bh[nq >> 1][(nq & 1) * 2];
                        const unsigned* blp = &bl[nq >> 1][(nq & 1) * 2];
                        mma_bf16(acc[mi][ni], ah[mi], bhp);  // hi*hi
                        mma_bf16(acc[mi][ni], al[mi], bhp);  // lo*hi
                        mma_bf16(acc[mi][ni], ah[mi], blp);  // hi*lo
                    }
            }
        }
    };

    issue(0);
    issue(1);
    issue(2);

    #pragma unroll 1
    for (int c = 0; c < NCHUNK; c++) {
        if (c < NCHUNK - 2)       { CP_WAIT2(); }
        else if (c == NCHUNK - 2) { CP_WAIT1(); }
        else                      { CP_WAIT0(); }
        __syncthreads();
        if (c + 3 < NCHUNK) issue(c + 3);
        compute(c & 3);
    }

    // Epilogue
    const int q  = lane >> 2;
    const int c4 = lane & 3;
    const bool soma = (n0 < MEM);   // BN=256 divides MEM -> uniform per CTA
    #pragma unroll
    for (int mi = 0; mi < 4; mi++) {
        int gm = m0 + wm + mi * 16 + q;
        #pragma unroll
        for (int ni = 0; ni < 8; ni++) {
            int gn = n0 + wn + ni * 8 + c4 * 2;
            float b0 = __ldg(bias + gn), b1 = __ldg(bias + gn + 1);
            #pragma unroll
            for (int rr = 0; rr < 2; rr++) {
                int row = gm + rr * 8;
                float v0 = acc[mi][ni][rr * 2 + 0] + b0;
                float v1 = acc[mi][ni][rr * 2 + 1] + b1;
                if (soma) {
                    v0 = 5.0f * ftanh(v0 * 0.2f);
                    v1 = 5.0f * ftanh(v1 * 0.2f);
                }
                *reinterpret_cast<float2*>(&g_emb[(size_t)row * NCOLS + gn]) =
                    make_float2(v0, v1);
            }
        }
    }
}

// ---------------------------------------------------------------- scan kernel
// 1 (b,mem) lane per thread, depth-4 register prefetch ring for MLP.
__global__ void __launch_bounds__(256) scan_kernel(
    const float* __restrict__ h0, float* __restrict__ out)
{
    int idx = blockIdx.x * 256 + threadIdx.x;  // 0 .. 131071
    int b = idx >> 10;
    int m = idx & (MEM - 1);
    const float* eb = g_emb + (size_t)b * LSEQ * NCOLS + m;
    float* ho = out + (size_t)b * LSEQ * MEM + m;

    float hf = h0[idx];
    float hs = h0[BATCH * MEM + idx];

    float sbq[4], ioq[4];
    #pragma unroll
    for (int d = 0; d < 4; d++) {
        sbq[d] = eb[(size_t)d * NCOLS];
        ioq[d] = eb[(size_t)d * NCOLS + MEM];
    }

    #pragma unroll 1
    for (int t = 0; t < LSEQ; t += 4) {
        #pragma unroll
        for (int j = 0; j < 4; j++) {
            float sb = sbq[j], io = ioq[j];
            int tn = t + j + 4;
            if (tn < LSEQ) {                      // prefetch 4 steps ahead
                sbq[j] = eb[(size_t)tn * NCOLS];
                ioq[j] = eb[(size_t)tn * NCOLS + MEM];
            }
            float d = hs + 0.4f;
            float arg = io + 4.0f * hf - 7.0f * (d * d) + sb;
            float hfn = ftanh(arg);
            float e2 = __expf(5.0f - 10.0f * hf);
            float eps = 0.9f + 0.9f * __fdividef(1.0f, 1.0f + e2);
            hs += eps * (hf - hs);
            hf = hfn;
            ho[(size_t)(t + j) * MEM] = hfn;
        }
    }
    out[(size_t)BATCH * LSEQ * MEM + idx] = hf;  // hf_last
}

// ---------------------------------------------------------------- launch
extern "C" void kernel_launch(void* const* d_in, const int* in_sizes, int n_in,
                              void* d_out, int out_size) {
    const float* u    = (const float*)d_in[0];  // [128, 512, 512]
    const float* h0   = (const float*)d_in[1];  // [2, 128, 1024]
    const float* W    = (const float*)d_in[2];  // [2048, 512]
    const float* bias = (const float*)d_in[3];  // [2048]
    float* out = (float*)d_out;                 // h_t [128,512,1024] ++ hf_last [128,1024]

    cudaFuncSetAttribute(gemm_kernel,
                         cudaFuncAttributeMaxDynamicSharedMemorySize, SMEM_TOTAL);

    split_u_kernel<<<(MROWS * KIN / 4) / 256, 256>>>((const float4*)u);
    split_w_kernel<<<(NCOLS * KIN / 4) / 256, 256>>>((const float4*)W);

    dim3 grid(NCOLS / BN, MROWS / BM);  // (8, 512): x-fastest -> A-strip L2 reuse
    gemm_kernel<<<grid, 256, SMEM_TOTAL>>>(bias);

    scan_kernel<<<(BATCH * MEM) / 256, 256>>>(h0, out);
}